// round 7
// baseline (speedup 1.0000x reference)
#include <cuda_runtime.h>
#include <cstdint>

// SSIM loss, fully fused — horizontal-first separable blur, f32x2 row-pair packing,
// cp.async pipelined triple-buffered smem, one barrier per 12-row chunk.
// ROWS=256 -> 576 CTAs = single wave on 148 SMs. Symmetric weights -> 6 packed regs.

#define IMG_H 1024
#define IMG_W 1024
#define W_OUT 118
#define EW    128          // blockDim.x
#define ROWS  256
#define CHUNK 12
#define NCHUNKS ((ROWS + CHUNK - 1) / CHUNK)      // 22 (last chunk: 4 rows)
#define NBLK  (9 * (IMG_H / ROWS) * 16)           // 576

typedef unsigned long long u64;

__device__ double g_acc = 0.0;
__device__ unsigned int g_cnt = 0u;

__device__ __forceinline__ u64 fma2(u64 a, u64 b, u64 c) {
    u64 d; asm("fma.rn.f32x2 %0, %1, %2, %3;" : "=l"(d) : "l"(a), "l"(b), "l"(c)); return d;
}
__device__ __forceinline__ u64 mul2(u64 a, u64 b) {
    u64 d; asm("mul.rn.f32x2 %0, %1, %2;" : "=l"(d) : "l"(a), "l"(b)); return d;
}
__device__ __forceinline__ u64 pack2(float lo, float hi) {
    u64 d; asm("mov.b64 %0, {%1, %2};" : "=l"(d) : "f"(lo), "f"(hi)); return d;
}
__device__ __forceinline__ void unpack2(u64 v, float& lo, float& hi) {
    asm("mov.b64 {%0, %1}, %2;" : "=f"(lo), "=f"(hi) : "l"(v));
}
__device__ __forceinline__ void cpa4(uint32_t dst, const float* src, bool ok) {
    unsigned sz = ok ? 4u : 0u;
    asm volatile("cp.async.ca.shared.global [%0], [%1], 4, %2;"
                 :: "r"(dst), "l"(src), "r"(sz));
}
#define CP_COMMIT() asm volatile("cp.async.commit_group;" ::: "memory")
#define CP_WAIT(n)  asm volatile("cp.async.wait_group %0;" :: "n"(n) : "memory")

__global__ __launch_bounds__(EW, 4) void ssim_kernel(const float* __restrict__ img1,
                                                     const float* __restrict__ img2,
                                                     float* __restrict__ out) {
    const float KW[11] = {
        0.0010283853f, 0.0075987626f, 0.0360007730f, 0.1093606900f,
        0.2130055300f, 0.2660117200f, 0.2130055300f, 0.1093606900f,
        0.0360007730f, 0.0075987626f, 0.0010283853f
    };
    // 6 distinct packed weights (kernel is symmetric): index via min(k, 10-k)
    u64 kw2[6];
    #pragma unroll
    for (int k = 0; k < 6; ++k) kw2[k] = pack2(KW[k], KW[k]);
#define KW2(k) kw2[(k) < 6 ? (k) : 10 - (k)]

    const int tid = threadIdx.x;
    const size_t base = (size_t)blockIdx.z * (size_t)(IMG_H * IMG_W);
    const int xg  = blockIdx.x * W_OUT - 5 + tid;
    const bool xok = (xg >= 0) && (xg < IMG_W);
    const int y0  = blockIdx.y * ROWS;
    const float* p1 = img1 + base + xg;
    const float* p2 = img2 + base + xg;

    __shared__ float2 sbuf[3][6][2][EW];   // [slot][row-pair][img][col] = 36 KB
    __shared__ float red[4];

    uint32_t sb;
    asm("{ .reg .u64 t; cvta.to.shared.u64 t, %1; cvt.u32.u64 %0, t; }"
        : "=r"(sb) : "l"((void*)&sbuf[0][0][0][0]));
    const uint32_t sbt = sb + (uint32_t)tid * 8u;

    float v1[12], v2[12], v3[12], v4[12], v5[12];
    const bool hok = (tid >= 5) && (tid < 5 + W_OUT) && (xg < IMG_W);
    float acc = 0.f;

    // ---------- issue prime (5 pairs -> slot 2) and chunk 0 (6 pairs -> slot 0) ----------
    #pragma unroll
    for (int i = 0; i < 5; ++i) {
        const int r0 = y0 - 5 + 2 * i, r1 = r0 + 1;
        const uint32_t d = sbt + 2u * 12288u + (uint32_t)i * 2048u;
        cpa4(d,          p1 + (size_t)r0 * IMG_W, xok && r0 >= 0);
        cpa4(d + 4u,     p1 + (size_t)r1 * IMG_W, xok && r1 >= 0);
        cpa4(d + 1024u,  p2 + (size_t)r0 * IMG_W, xok && r0 >= 0);
        cpa4(d + 1028u,  p2 + (size_t)r1 * IMG_W, xok && r1 >= 0);
    }
    CP_COMMIT();
    #pragma unroll
    for (int j = 0; j < 6; ++j) {
        const int r0 = y0 + 5 + 2 * j, r1 = r0 + 1;
        const uint32_t d = sbt + (uint32_t)j * 2048u;
        cpa4(d,          p1 + (size_t)r0 * IMG_W, xok && r0 < IMG_H);
        cpa4(d + 4u,     p1 + (size_t)r1 * IMG_W, xok && r1 < IMG_H);
        cpa4(d + 1024u,  p2 + (size_t)r0 * IMG_W, xok && r0 < IMG_H);
        cpa4(d + 1028u,  p2 + (size_t)r1 * IMG_W, xok && r1 < IMG_H);
    }
    CP_COMMIT();
    CP_WAIT(1);
    __syncthreads();

    // ---------- prime horizontal: 5 pairs (slot 2) -> ring elements 0..9 ----------
    if (hok) {
        #pragma unroll
        for (int i = 0; i < 5; ++i) {
            u64 h1 = 0, h2 = 0, h3 = 0, h4 = 0, h5 = 0;
            #pragma unroll
            for (int k = 0; k < 11; ++k) {
                const u64 A = *(const u64*)&sbuf[2][i][0][tid - 5 + k];
                const u64 B = *(const u64*)&sbuf[2][i][1][tid - 5 + k];
                const u64 w = KW2(k);
                const u64 ta = mul2(w, A);
                const u64 tb = mul2(w, B);
                h1 = fma2(w, A, h1);
                h2 = fma2(w, B, h2);
                h3 = fma2(ta, A, h3);
                h4 = fma2(tb, B, h4);
                h5 = fma2(ta, B, h5);
            }
            unpack2(h1, v1[2*i], v1[2*i+1]);
            unpack2(h2, v2[2*i], v2[2*i+1]);
            unpack2(h3, v3[2*i], v3[2*i+1]);
            unpack2(h4, v4[2*i], v4[2*i+1]);
            unpack2(h5, v5[2*i], v5[2*i+1]);
        }
    }
    v1[10] = v2[10] = v3[10] = v4[10] = v5[10] = 0.f;
    v1[11] = v2[11] = v3[11] = v4[11] = v5[11] = 0.f;

    // ---------- main loop: one barrier per 12-row chunk ----------
    for (int c = 0; c < NCHUNKS; ++c) {
        const int rb = c * CHUNK;
        const int slot = c % 3;

        if (c + 1 < NCHUNKS) {
            const int ns = (c + 1) % 3;
            const int rb2 = rb + CHUNK;
            #pragma unroll
            for (int j = 0; j < 6; ++j) {
                if (rb2 + 2 * j < ROWS) {
                    const int r0 = y0 + rb2 + 5 + 2 * j, r1 = r0 + 1;
                    const uint32_t d = sbt + (uint32_t)ns * 12288u + (uint32_t)j * 2048u;
                    cpa4(d,         p1 + (size_t)r0 * IMG_W, xok && r0 < IMG_H);
                    cpa4(d + 4u,    p1 + (size_t)r1 * IMG_W, xok && r1 < IMG_H);
                    cpa4(d + 1024u, p2 + (size_t)r0 * IMG_W, xok && r0 < IMG_H);
                    cpa4(d + 1028u, p2 + (size_t)r1 * IMG_W, xok && r1 < IMG_H);
                }
            }
            CP_COMMIT();
            CP_WAIT(1);
        } else {
            CP_WAIT(0);
        }
        __syncthreads();

        if (hok) {
            #pragma unroll
            for (int j = 0; j < 6; ++j) {
                if (rb + 2 * j < ROWS) {
                    u64 h1 = 0, h2 = 0, h3 = 0, h4 = 0, h5 = 0;
                    #pragma unroll
                    for (int k = 0; k < 11; ++k) {
                        const u64 A = *(const u64*)&sbuf[slot][j][0][tid - 5 + k];
                        const u64 B = *(const u64*)&sbuf[slot][j][1][tid - 5 + k];
                        const u64 w = KW2(k);
                        const u64 ta = mul2(w, A);
                        const u64 tb = mul2(w, B);
                        h1 = fma2(w, A, h1);
                        h2 = fma2(w, B, h2);
                        h3 = fma2(ta, A, h3);
                        h4 = fma2(tb, B, h4);
                        h5 = fma2(ta, B, h5);
                    }
                    const int sA = (2 * j + 10) % 12;       // compile-time
                    const int sB = (2 * j + 11) % 12;
                    unpack2(h1, v1[sA], v1[sB]);
                    unpack2(h2, v2[sA], v2[sB]);
                    unpack2(h3, v3[sA], v3[sB]);
                    unpack2(h4, v4[sA], v4[sB]);
                    unpack2(h5, v5[sA], v5[sB]);

                    #pragma unroll
                    for (int q = 0; q < 2; ++q) {
                        float m1 = 0.f, m2 = 0.f, m3 = 0.f, m4 = 0.f, m5 = 0.f;
                        #pragma unroll
                        for (int d = 0; d < 11; ++d) {
                            const int s = (2 * j + q + d) % 12;   // compile-time
                            m1 = fmaf(KW[d], v1[s], m1);
                            m2 = fmaf(KW[d], v2[s], m2);
                            m3 = fmaf(KW[d], v3[s], m3);
                            m4 = fmaf(KW[d], v4[s], m4);
                            m5 = fmaf(KW[d], v5[s], m5);
                        }
                        const float mu1s = m1 * m1;
                        const float mu2s = m2 * m2;
                        const float mu12 = m1 * m2;
                        const float num = fmaf(2.f, mu12, 0.0001f) *
                                          fmaf(2.f, m5 - mu12, 0.0009f);
                        const float den = (mu1s + mu2s + 0.0001f) *
                                          ((m3 - mu1s) + (m4 - mu2s) + 0.0009f);
                        acc += __fdividef(num, den);
                    }
                }
            }
        }
    }

    // ---------- reduction + last-block finalize ----------
    #pragma unroll
    for (int o = 16; o; o >>= 1) acc += __shfl_xor_sync(0xffffffffu, acc, o);
    if ((tid & 31) == 0) red[tid >> 5] = acc;
    __syncthreads();
    if (tid == 0) {
        const double t = (double)(red[0] + red[1] + red[2] + red[3]);
        atomicAdd(&g_acc, t);
        __threadfence();
        const unsigned int n = atomicAdd(&g_cnt, 1u);
        if (n == NBLK - 1) {
            const double total = atomicAdd(&g_acc, 0.0);
            out[0] = (float)(1.0 - total / 16777216.0);
            atomicExch((unsigned long long*)&g_acc, 0ull);
            atomicExch(&g_cnt, 0u);
        }
    }
}

extern "C" void kernel_launch(void* const* d_in, const int* in_sizes, int n_in,
                              void* d_out, int out_size) {
    const float* img1 = (const float*)d_in[0];
    const float* img2 = (const float*)d_in[1];
    float* out = (float*)d_out;

    dim3 grid((IMG_W + W_OUT - 1) / W_OUT, IMG_H / ROWS, 16);  // (9, 4, 16)
    ssim_kernel<<<grid, EW>>>(img1, img2, out);
}

// round 8
// speedup vs baseline: 1.0161x; 1.0161x over previous
#include <cuda_runtime.h>
#include <cstdint>

// SSIM loss, fully fused — horizontal-first separable blur, f32x2 row-pair packing,
// cp.async pipelined triple-buffered raw smem + single-buffered ss=(a²+b²) smem field.
// 4 blur fields {a, b, a²+b², ab} (SSIM only needs sigma1+sigma2). Vertical FFMA-imm rings.

#define IMG_H 1024
#define IMG_W 1024
#define W_OUT 118
#define EW    128          // blockDim.x
#define ROWS  256
#define CHUNK 12
#define NCHUNKS ((ROWS + CHUNK - 1) / CHUNK)      // 22 (last chunk: 4 rows)
#define NBLK  (9 * (IMG_H / ROWS) * 16)           // 576

typedef unsigned long long u64;

__device__ double g_acc = 0.0;
__device__ unsigned int g_cnt = 0u;

__device__ __forceinline__ u64 fma2(u64 a, u64 b, u64 c) {
    u64 d; asm("fma.rn.f32x2 %0, %1, %2, %3;" : "=l"(d) : "l"(a), "l"(b), "l"(c)); return d;
}
__device__ __forceinline__ u64 mul2(u64 a, u64 b) {
    u64 d; asm("mul.rn.f32x2 %0, %1, %2;" : "=l"(d) : "l"(a), "l"(b)); return d;
}
__device__ __forceinline__ u64 add2(u64 a, u64 b) {
    u64 d; asm("add.rn.f32x2 %0, %1, %2;" : "=l"(d) : "l"(a), "l"(b)); return d;
}
__device__ __forceinline__ u64 pack2(float lo, float hi) {
    u64 d; asm("mov.b64 %0, {%1, %2};" : "=l"(d) : "f"(lo), "f"(hi)); return d;
}
__device__ __forceinline__ void unpack2(u64 v, float& lo, float& hi) {
    asm("mov.b64 {%0, %1}, %2;" : "=f"(lo), "=f"(hi) : "l"(v));
}
__device__ __forceinline__ void cpa4(uint32_t dst, const float* src, bool ok) {
    unsigned sz = ok ? 4u : 0u;
    asm volatile("cp.async.ca.shared.global [%0], [%1], 4, %2;"
                 :: "r"(dst), "l"(src), "r"(sz));
}
#define CP_COMMIT() asm volatile("cp.async.commit_group;" ::: "memory")
#define CP_WAIT(n)  asm volatile("cp.async.wait_group %0;" :: "n"(n) : "memory")

__global__ __launch_bounds__(EW, 4) void ssim_kernel(const float* __restrict__ img1,
                                                     const float* __restrict__ img2,
                                                     float* __restrict__ out) {
    const float KW[11] = {
        0.0010283853f, 0.0075987626f, 0.0360007730f, 0.1093606900f,
        0.2130055300f, 0.2660117200f, 0.2130055300f, 0.1093606900f,
        0.0360007730f, 0.0075987626f, 0.0010283853f
    };
    u64 kw2[6];   // symmetric kernel: 6 distinct packed weights
    #pragma unroll
    for (int k = 0; k < 6; ++k) kw2[k] = pack2(KW[k], KW[k]);
#define KW2(k) kw2[(k) < 6 ? (k) : 10 - (k)]

    const int tid = threadIdx.x;
    const size_t base = (size_t)blockIdx.z * (size_t)(IMG_H * IMG_W);
    const int xg  = blockIdx.x * W_OUT - 5 + tid;
    const bool xok = (xg >= 0) && (xg < IMG_W);
    const int y0  = blockIdx.y * ROWS;
    const float* p1 = img1 + base + xg;
    const float* p2 = img2 + base + xg;

    __shared__ float2 sab[3][6][2][EW];   // triple-buffered raw rows: 36 KB
    __shared__ float2 sss[6][EW];         // single-buffered a^2+b^2:   6 KB
    __shared__ float red[4];

    uint32_t sb;
    asm("{ .reg .u64 t; cvta.to.shared.u64 t, %1; cvt.u32.u64 %0, t; }"
        : "=r"(sb) : "l"((void*)&sab[0][0][0][0]));
    const uint32_t sbt = sb + (uint32_t)tid * 8u;
    // byte offsets within sab: slot*12288 + pair*2048 + img*1024 (+4 second row)

    float v1[12], v2[12], v3[12], v5[12];   // vertical rings: mu1, mu2, ss, ab
    const bool hok = (tid >= 5) && (tid < 5 + W_OUT) && (xg < IMG_W);
    float acc = 0.f;

    // ---------- issue prime (5 pairs -> slot 2) and chunk 0 (6 pairs -> slot 0) ----------
    #pragma unroll
    for (int i = 0; i < 5; ++i) {
        const int r0 = y0 - 5 + 2 * i, r1 = r0 + 1;
        const uint32_t d = sbt + 2u * 12288u + (uint32_t)i * 2048u;
        cpa4(d,          p1 + (size_t)r0 * IMG_W, xok && r0 >= 0);
        cpa4(d + 4u,     p1 + (size_t)r1 * IMG_W, xok && r1 >= 0);
        cpa4(d + 1024u,  p2 + (size_t)r0 * IMG_W, xok && r0 >= 0);
        cpa4(d + 1028u,  p2 + (size_t)r1 * IMG_W, xok && r1 >= 0);
    }
    CP_COMMIT();
    #pragma unroll
    for (int j = 0; j < 6; ++j) {
        const int r0 = y0 + 5 + 2 * j, r1 = r0 + 1;
        const uint32_t d = sbt + (uint32_t)j * 2048u;
        cpa4(d,          p1 + (size_t)r0 * IMG_W, xok && r0 < IMG_H);
        cpa4(d + 4u,     p1 + (size_t)r1 * IMG_W, xok && r1 < IMG_H);
        cpa4(d + 1024u,  p2 + (size_t)r0 * IMG_W, xok && r0 < IMG_H);
        cpa4(d + 1028u,  p2 + (size_t)r1 * IMG_W, xok && r1 < IMG_H);
    }
    CP_COMMIT();
    CP_WAIT(1);
    __syncthreads();

    // ---------- prime: ss then horizontal for 5 pairs (slot 2) -> ring 0..9 ----------
    #pragma unroll
    for (int i = 0; i < 5; ++i) {
        const u64 A = *(const u64*)&sab[2][i][0][tid];
        const u64 B = *(const u64*)&sab[2][i][1][tid];
        *(u64*)&sss[i][tid] = fma2(A, A, mul2(B, B));
    }
    __syncthreads();
    if (hok) {
        #pragma unroll
        for (int i = 0; i < 5; ++i) {
            u64 h1 = 0, h2 = 0, h3 = 0, h5 = 0;
            #pragma unroll
            for (int k = 0; k < 11; ++k) {
                const u64 A = *(const u64*)&sab[2][i][0][tid - 5 + k];
                const u64 B = *(const u64*)&sab[2][i][1][tid - 5 + k];
                const u64 S = *(const u64*)&sss[i][tid - 5 + k];
                const u64 w = KW2(k);
                const u64 ta = mul2(w, A);
                h1 = add2(h1, ta);
                h2 = fma2(w, B, h2);
                h3 = fma2(w, S, h3);
                h5 = fma2(ta, B, h5);
            }
            unpack2(h1, v1[2*i], v1[2*i+1]);
            unpack2(h2, v2[2*i], v2[2*i+1]);
            unpack2(h3, v3[2*i], v3[2*i+1]);
            unpack2(h5, v5[2*i], v5[2*i+1]);
        }
    }
    v1[10] = v2[10] = v3[10] = v5[10] = 0.f;
    v1[11] = v2[11] = v3[11] = v5[11] = 0.f;

    // ---------- main loop: 12-row chunks ----------
    for (int c = 0; c < NCHUNKS; ++c) {
        const int rb = c * CHUNK;
        const int slot = c % 3;

        if (c + 1 < NCHUNKS) {
            const int ns = (c + 1) % 3;
            const int rb2 = rb + CHUNK;
            #pragma unroll
            for (int j = 0; j < 6; ++j) {
                if (rb2 + 2 * j < ROWS) {
                    const int r0 = y0 + rb2 + 5 + 2 * j, r1 = r0 + 1;
                    const uint32_t d = sbt + (uint32_t)ns * 12288u + (uint32_t)j * 2048u;
                    cpa4(d,         p1 + (size_t)r0 * IMG_W, xok && r0 < IMG_H);
                    cpa4(d + 4u,    p1 + (size_t)r1 * IMG_W, xok && r1 < IMG_H);
                    cpa4(d + 1024u, p2 + (size_t)r0 * IMG_W, xok && r0 < IMG_H);
                    cpa4(d + 1028u, p2 + (size_t)r1 * IMG_W, xok && r1 < IMG_H);
                }
            }
            CP_COMMIT();
            CP_WAIT(1);
        } else {
            CP_WAIT(0);
        }
        __syncthreads();   // chunk c visible; slot (c+1)%3 free; sss readers (c-1) done

        // ss = a^2 + b^2 for this chunk (all 128 columns)
        #pragma unroll
        for (int j = 0; j < 6; ++j) {
            if (rb + 2 * j < ROWS) {
                const u64 A = *(const u64*)&sab[slot][j][0][tid];
                const u64 B = *(const u64*)&sab[slot][j][1][tid];
                *(u64*)&sss[j][tid] = fma2(A, A, mul2(B, B));
            }
        }
        __syncthreads();

        if (hok) {
            #pragma unroll
            for (int j = 0; j < 6; ++j) {
                if (rb + 2 * j < ROWS) {
                    u64 h1 = 0, h2 = 0, h3 = 0, h5 = 0;
                    #pragma unroll
                    for (int k = 0; k < 11; ++k) {
                        const u64 A = *(const u64*)&sab[slot][j][0][tid - 5 + k];
                        const u64 B = *(const u64*)&sab[slot][j][1][tid - 5 + k];
                        const u64 S = *(const u64*)&sss[j][tid - 5 + k];
                        const u64 w = KW2(k);
                        const u64 ta = mul2(w, A);
                        h1 = add2(h1, ta);
                        h2 = fma2(w, B, h2);
                        h3 = fma2(w, S, h3);
                        h5 = fma2(ta, B, h5);
                    }
                    const int sA = (2 * j + 10) % 12;       // compile-time
                    const int sB = (2 * j + 11) % 12;
                    unpack2(h1, v1[sA], v1[sB]);
                    unpack2(h2, v2[sA], v2[sB]);
                    unpack2(h3, v3[sA], v3[sB]);
                    unpack2(h5, v5[sA], v5[sB]);

                    #pragma unroll
                    for (int q = 0; q < 2; ++q) {
                        float m1 = 0.f, m2 = 0.f, m3 = 0.f, m5 = 0.f;
                        #pragma unroll
                        for (int d = 0; d < 11; ++d) {
                            const int s = (2 * j + q + d) % 12;   // compile-time
                            m1 = fmaf(KW[d], v1[s], m1);
                            m2 = fmaf(KW[d], v2[s], m2);
                            m3 = fmaf(KW[d], v3[s], m3);
                            m5 = fmaf(KW[d], v5[s], m5);
                        }
                        const float mu1s = m1 * m1;
                        const float mu2s = m2 * m2;
                        const float mu12 = m1 * m2;
                        const float num = fmaf(2.f, mu12, 0.0001f) *
                                          fmaf(2.f, m5 - mu12, 0.0009f);
                        const float den = (mu1s + mu2s + 0.0001f) *
                                          ((m3 - mu1s - mu2s) + 0.0009f);
                        acc += __fdividef(num, den);
                    }
                }
            }
        }
    }

    // ---------- reduction + last-block finalize ----------
    #pragma unroll
    for (int o = 16; o; o >>= 1) acc += __shfl_xor_sync(0xffffffffu, acc, o);
    if ((tid & 31) == 0) red[tid >> 5] = acc;
    __syncthreads();
    if (tid == 0) {
        const double t = (double)(red[0] + red[1] + red[2] + red[3]);
        atomicAdd(&g_acc, t);
        __threadfence();
        const unsigned int n = atomicAdd(&g_cnt, 1u);
        if (n == NBLK - 1) {
            const double total = atomicAdd(&g_acc, 0.0);
            out[0] = (float)(1.0 - total / 16777216.0);
            atomicExch((unsigned long long*)&g_acc, 0ull);
            atomicExch(&g_cnt, 0u);
        }
    }
}

extern "C" void kernel_launch(void* const* d_in, const int* in_sizes, int n_in,
                              void* d_out, int out_size) {
    const float* img1 = (const float*)d_in[0];
    const float* img2 = (const float*)d_in[1];
    float* out = (float*)d_out;

    dim3 grid((IMG_W + W_OUT - 1) / W_OUT, IMG_H / ROWS, 16);  // (9, 4, 16)
    ssim_kernel<<<grid, EW>>>(img1, img2, out);
}